// round 4
// baseline (speedup 1.0000x reference)
#include <cuda_runtime.h>
#include <cuda_fp16.h>
#include <cstdint>

// Problem constants
#define B_  8
#define T_  256
#define U_  64
#define D_  512
#define V_  1024

// Tiling
#define BM 128
#define BN 128
#define KC 64
#define S_STRIDE (KC + 8)   // 72 halves -> 144B row stride, conflict-free for ldmatrix

// Pre-converted fp16 weights (scratch; allocation-free per harness rules)
__device__ __align__(16) __half g_W16[V_ * D_];

__global__ void convert_w_kernel(const float* __restrict__ W) {
    int i = (blockIdx.x * blockDim.x + threadIdx.x) * 4;  // V_*D_ = 524288, grid covers exactly
    float4 w = *(const float4*)(W + i);
    union { __half2 h[2]; uint2 u; } pack;
    pack.h[0] = __floats2half2_rn(w.x, w.y);
    pack.h[1] = __floats2half2_rn(w.z, w.w);
    *(uint2*)(g_W16 + i) = pack.u;
}

// Pass-through outputs: harness flattens all outputs into one float32 buffer,
// so the int32 length vectors must be VALUE-converted to float, not bit-copied.
__global__ void write_lengths_kernel(const int* __restrict__ slen,
                                     const int* __restrict__ tlen,
                                     float* __restrict__ out_tail) {
    int i = threadIdx.x;
    if (i < B_)            out_tail[i]      = (float)slen[i];
    else if (i < 2 * B_)   out_tail[i]      = (float)tlen[i - B_];
}

__global__ __launch_bounds__(256)
void joiner_gemm_kernel(const float* __restrict__ src,
                        const float* __restrict__ tgt,
                        const float* __restrict__ bias,
                        float* __restrict__ out)
{
    __shared__ __half As[BM * S_STRIDE];
    __shared__ __half Bs[BN * S_STRIDE];

    const int tid  = threadIdx.x;
    const int lane = tid & 31;
    const int warp = tid >> 5;
    const int warp_row = warp >> 2;   // 0..1 : 64 rows each
    const int warp_col = warp & 3;    // 0..3 : 32 cols each

    const int m0 = blockIdx.y * BM;
    const int v0 = blockIdx.x * BN;
    const int b  = m0 >> 14;              // / (T_*U_) = /16384
    const int t0 = (m0 & 16383) >> 6;     // / U_

    // A-fill thread mapping: 16 k-groups (float4) x 16 row-groups (8 rows each)
    const int kg = tid & 15;              // k-group: k = kg*4 within KC
    const int rg = tid >> 4;              // row group: rows rg*8 .. rg*8+7
    const int t_idx = t0 + (rg >> 3);     // rows 0..63 -> t0, 64..127 -> t0+1
    const float* src_row  = src + (size_t)(b * T_ + t_idx) * D_ + kg * 4;
    const float* tgt_base = tgt + (size_t)(b * U_) * D_ + kg * 4;

    float acc[4][4][4];
    #pragma unroll
    for (int i = 0; i < 4; ++i)
        #pragma unroll
        for (int j = 0; j < 4; ++j)
            #pragma unroll
            for (int k = 0; k < 4; ++k) acc[i][j][k] = 0.f;

    for (int k0 = 0; k0 < D_; k0 += KC) {
        // ---- Fill A tile: relu(src + tgt) -> fp16 ----
        float4 s4 = *(const float4*)(src_row + k0);
        #pragma unroll
        for (int j = 0; j < 8; ++j) {
            int row = rg * 8 + j;
            int u = row & 63;
            float4 g4 = *(const float4*)(tgt_base + (size_t)u * D_ + k0);
            float x0 = fmaxf(s4.x + g4.x, 0.f);
            float x1 = fmaxf(s4.y + g4.y, 0.f);
            float x2 = fmaxf(s4.z + g4.z, 0.f);
            float x3 = fmaxf(s4.w + g4.w, 0.f);
            union { __half2 h[2]; uint2 u2; } pack;
            pack.h[0] = __floats2half2_rn(x0, x1);
            pack.h[1] = __floats2half2_rn(x2, x3);
            *(uint2*)(As + row * S_STRIDE + kg * 4) = pack.u2;
        }
        // ---- Fill B tile from fp16 weights: 128 rows x 16 groups ----
        #pragma unroll
        for (int it = 0; it < 8; ++it) {
            int i = tid + it * 256;
            int n = i >> 4;
            int g = i & 15;
            uint2 w = *(const uint2*)(g_W16 + (size_t)(v0 + n) * D_ + k0 + g * 4);
            *(uint2*)(Bs + n * S_STRIDE + g * 4) = w;
        }
        __syncthreads();

        // ---- Compute: 4 k-steps of 16 ----
        #pragma unroll
        for (int kk = 0; kk < KC; kk += 16) {
            uint32_t afr[4][4], bfr[4][2];
            #pragma unroll
            for (int mt = 0; mt < 4; ++mt) {
                int row = warp_row * 64 + mt * 16 + (lane & 15);
                int col = kk + ((lane >> 4) << 3);
                uint32_t addr = (uint32_t)__cvta_generic_to_shared(As + row * S_STRIDE + col);
                asm volatile("ldmatrix.sync.aligned.m8n8.x4.shared.b16 {%0,%1,%2,%3}, [%4];"
                             : "=r"(afr[mt][0]), "=r"(afr[mt][1]), "=r"(afr[mt][2]), "=r"(afr[mt][3])
                             : "r"(addr));
            }
            #pragma unroll
            for (int nt = 0; nt < 4; ++nt) {
                int row = warp_col * 32 + nt * 8 + (lane & 7);
                int col = kk + (((lane >> 3) & 1) << 3);
                uint32_t addr = (uint32_t)__cvta_generic_to_shared(Bs + row * S_STRIDE + col);
                asm volatile("ldmatrix.sync.aligned.m8n8.x2.shared.b16 {%0,%1}, [%2];"
                             : "=r"(bfr[nt][0]), "=r"(bfr[nt][1])
                             : "r"(addr));
            }
            #pragma unroll
            for (int mt = 0; mt < 4; ++mt)
                #pragma unroll
                for (int nt = 0; nt < 4; ++nt) {
                    asm volatile(
                        "mma.sync.aligned.m16n8k16.row.col.f32.f16.f16.f32 "
                        "{%0,%1,%2,%3}, {%4,%5,%6,%7}, {%8,%9}, {%0,%1,%2,%3};"
                        : "+f"(acc[mt][nt][0]), "+f"(acc[mt][nt][1]),
                          "+f"(acc[mt][nt][2]), "+f"(acc[mt][nt][3])
                        : "r"(afr[mt][0]), "r"(afr[mt][1]), "r"(afr[mt][2]), "r"(afr[mt][3]),
                          "r"(bfr[nt][0]), "r"(bfr[nt][1]));
                }
        }
        __syncthreads();
    }

    // ---- Epilogue: add bias, store fp32 ----
    #pragma unroll
    for (int nt = 0; nt < 4; ++nt) {
        int col = v0 + warp_col * 32 + nt * 8 + ((lane & 3) << 1);
        float2 bv = *(const float2*)(bias + col);
        #pragma unroll
        for (int mt = 0; mt < 4; ++mt) {
            int row = m0 + warp_row * 64 + mt * 16 + (lane >> 2);
            float2 r0 = make_float2(acc[mt][nt][0] + bv.x, acc[mt][nt][1] + bv.y);
            float2 r1 = make_float2(acc[mt][nt][2] + bv.x, acc[mt][nt][3] + bv.y);
            *(float2*)(out + (size_t)row * V_ + col)       = r0;
            *(float2*)(out + (size_t)(row + 8) * V_ + col) = r1;
        }
    }
}

extern "C" void kernel_launch(void* const* d_in, const int* in_sizes, int n_in,
                              void* d_out, int out_size) {
    const float* src  = (const float*)d_in[0];
    const int*   slen = (const int*)  d_in[1];
    const float* tgt  = (const float*)d_in[2];
    const int*   tlen = (const int*)  d_in[3];
    const float* W    = (const float*)d_in[4];
    const float* bias = (const float*)d_in[5];
    float* out = (float*)d_out;

    // 1) Convert W -> fp16 scratch (524288 elems / 4 per thread = 131072 threads)
    convert_w_kernel<<<512, 256>>>(W);

    // 2) Fused relu(src+tgt) GEMM
    dim3 grid(V_ / BN, (B_ * T_ * U_) / BM);   // (8, 1024)
    joiner_gemm_kernel<<<grid, 256>>>(src, tgt, bias, out);

    // 3) Pass-through length outputs, VALUE-converted to the float32 output
    //    buffer dtype (bit-copy fails: int bits read back as denormals).
    const long long N_OUT = (long long)B_ * T_ * U_ * V_;   // 134217728
    if ((long long)out_size >= N_OUT + 2 * B_) {
        write_lengths_kernel<<<1, 32>>>(slen, tlen, out + N_OUT);
    }
}